// round 1
// baseline (speedup 1.0000x reference)
#include <cuda_runtime.h>
#include <math.h>
#include <stdint.h>

#define BATCH    2048
#define IN_DIM   2048
#define POOLN    32768
#define HIDN     1024
#define MAXP     8192
#define MINP     512

// ---------------- scratch (device globals: no allocations allowed) ----------
__device__ float g_c1[BATCH * 128];
__device__ float g_h[BATCH * HIDN];
__device__ float g_scores[(size_t)BATCH * POOLN];   // 256 MB
__device__ float g_comp[BATCH];
__device__ int   g_budget;

// ---------------- fp32 tiled GEMM: C = epi(A[MxK] @ B[KxN]) ------------------
// epi==0 : C = relu(acc + bias[col])
// epi==1 : C = (acc + bias[col]) + noise[row*N+col]*0.1f   (roundings separate)
__global__ void __launch_bounds__(256) sgemm128(
    const float* __restrict__ A, const float* __restrict__ B,
    const float* __restrict__ bias, const float* __restrict__ noise,
    float* __restrict__ C, int M, int N, int K, int epi)
{
    __shared__ float As[16][128];
    __shared__ float Bs[16][128];

    const int bx = blockIdx.x, by = blockIdx.y;
    const int tid = threadIdx.x;
    const int tn = tid & 15;        // 0..15  (col group)
    const int tm = tid >> 4;        // 0..15  (row group)

    const float* Ab = A + (size_t)by * 128 * K;
    const float* Bb = B + (size_t)bx * 128;

    float acc[8][8];
#pragma unroll
    for (int i = 0; i < 8; i++)
#pragma unroll
        for (int j = 0; j < 8; j++) acc[i][j] = 0.0f;

    for (int k0 = 0; k0 < K; k0 += 16) {
        // load A tile 128x16 (each thread: 2 float4)
#pragma unroll
        for (int l = 0; l < 2; l++) {
            int pos = tid * 2 + l;           // 0..511
            int r = pos >> 2, c4 = pos & 3;  // 128 rows x 4 float4
            float4 v = *(const float4*)(Ab + (size_t)r * K + k0 + c4 * 4);
            As[c4 * 4 + 0][r] = v.x;
            As[c4 * 4 + 1][r] = v.y;
            As[c4 * 4 + 2][r] = v.z;
            As[c4 * 4 + 3][r] = v.w;
        }
        // load B tile 16x128 (each thread: 2 float4, fully coalesced)
#pragma unroll
        for (int l = 0; l < 2; l++) {
            int pos = tid * 2 + l;            // 0..511
            int r = pos >> 5, c4 = pos & 31;  // 16 rows x 32 float4
            *(float4*)&Bs[r][c4 * 4] = *(const float4*)(Bb + (size_t)(k0 + r) * N + c4 * 4);
        }
        __syncthreads();

#pragma unroll
        for (int k = 0; k < 16; k++) {
            float a[8], b[8];
            const float4* a4 = (const float4*)&As[k][tm * 8];
            const float4* b4 = (const float4*)&Bs[k][tn * 8];
            float4 av0 = a4[0], av1 = a4[1];
            float4 bv0 = b4[0], bv1 = b4[1];
            a[0]=av0.x; a[1]=av0.y; a[2]=av0.z; a[3]=av0.w;
            a[4]=av1.x; a[5]=av1.y; a[6]=av1.z; a[7]=av1.w;
            b[0]=bv0.x; b[1]=bv0.y; b[2]=bv0.z; b[3]=bv0.w;
            b[4]=bv1.x; b[5]=bv1.y; b[6]=bv1.z; b[7]=bv1.w;
#pragma unroll
            for (int i = 0; i < 8; i++)
#pragma unroll
                for (int j = 0; j < 8; j++) acc[i][j] += a[i] * b[j];
        }
        __syncthreads();
    }

#pragma unroll
    for (int i = 0; i < 8; i++) {
        int row = by * 128 + tm * 8 + i;
#pragma unroll
        for (int j = 0; j < 8; j++) {
            int col = bx * 128 + tn * 8 + j;
            float v = acc[i][j];
            if (epi == 0) {
                v = fmaxf(__fadd_rn(v, bias[col]), 0.0f);
            } else {
                v = __fadd_rn(v, bias[col]);
                float nz = __fmul_rn(noise[(size_t)row * N + col], 0.1f);
                v = __fadd_rn(v, nz);
            }
            C[(size_t)row * N + col] = v;
        }
    }
}

// ---------------- comp stage 2: sigmoid(c1 @ W2c + b2c) ----------------------
__global__ void comp_kernel(const float* __restrict__ W2c,
                            const float* __restrict__ b2c,
                            float* __restrict__ out_comp)
{
    int row  = blockIdx.x * 8 + (threadIdx.x >> 5);
    int lane = threadIdx.x & 31;
    float p = 0.0f;
#pragma unroll
    for (int t = lane; t < 128; t += 32) p += g_c1[row * 128 + t] * W2c[t];
#pragma unroll
    for (int o = 16; o > 0; o >>= 1) p += __shfl_down_sync(0xffffffffu, p, o);
    if (lane == 0) {
        float z = p + b2c[0];
        float c = 1.0f / (1.0f + expf(-z));
        g_comp[row]  = c;
        out_comp[row] = c;
    }
}

// ---------------- budget --------------------------------------------------
__global__ void budget_kernel(float* __restrict__ out_budget)
{
    __shared__ float ws[32];
    int tid = threadIdx.x;
    float s = g_comp[tid] + g_comp[tid + 1024];
#pragma unroll
    for (int o = 16; o > 0; o >>= 1) s += __shfl_down_sync(0xffffffffu, s, o);
    if ((tid & 31) == 0) ws[tid >> 5] = s;
    __syncthreads();
    if (tid < 32) {
        float v = ws[tid];
#pragma unroll
        for (int o = 16; o > 0; o >>= 1) v += __shfl_down_sync(0xffffffffu, v, o);
        if (tid == 0) {
            float mean  = v / 2048.0f;
            float scale = mean * mean;                 // EXP = 2.0
            float t = 512.0f + 7680.0f * scale;
            int b = (int)floorf(t);
            if (b < MINP) b = MINP;
            if (b > MAXP) b = MAXP;
            g_budget = b;
            out_budget[0] = (float)b;
        }
    }
}

// ---------------- top-k + softmax -----------------------------------------
__device__ __forceinline__ unsigned f2key(float s) {
    unsigned b = __float_as_uint(s);
    return (b & 0x80000000u) ? ~b : (b | 0x80000000u);   // order-preserving
}
__device__ __forceinline__ float key2f(unsigned k) {
    return __uint_as_float((k & 0x80000000u) ? (k ^ 0x80000000u) : ~k);
}

// smem: keys u32[32768] | sbuf u64[8192] | red i32[128]
#define TOPK_SMEM (131072 + 65536 + 512)

__global__ void __launch_bounds__(1024) topk_kernel(
    float* __restrict__ out_idx, float* __restrict__ out_w)
{
    extern __shared__ unsigned char smem_raw[];
    unsigned*           keys = (unsigned*)smem_raw;
    unsigned long long* sbuf = (unsigned long long*)(smem_raw + 131072);
    int*                red  = (int*)(smem_raw + 131072 + 65536);
    float*              fred = (float*)red;

    const int row = blockIdx.x;
    const int tid = threadIdx.x;
    const int warp = tid >> 5, lane = tid & 31;
    const float* srow = g_scores + (size_t)row * POOLN;

    // load + transform
    for (int j = tid; j < POOLN; j += 1024) keys[j] = f2key(srow[j]);
    __syncthreads();

    // exact k-th largest key: minimal t with count(key > t) < 8192
    unsigned lo = 0u, hi = 0xFFFFFFFFu;
    while (lo < hi) {
        unsigned mid = lo + ((hi - lo) >> 1);
        int c = 0;
#pragma unroll 8
        for (int j = tid; j < POOLN; j += 1024) c += (keys[j] > mid) ? 1 : 0;
#pragma unroll
        for (int o = 16; o > 0; o >>= 1) c += __shfl_down_sync(0xffffffffu, c, o);
        __syncthreads();
        if (tid == 0) red[0] = 0;
        __syncthreads();
        if (lane == 0) atomicAdd(&red[0], c);
        __syncthreads();
        int total = red[0];
        if (total < MAXP) hi = mid; else lo = mid + 1;
    }
    const unsigned V = lo;

    // per-thread contiguous chunk (preserves ascending idx order for ties)
    const int beg = tid * 32;
    int cgt = 0, ceq = 0;
#pragma unroll 8
    for (int j = beg; j < beg + 32; j++) {
        unsigned k = keys[j];
        cgt += (k > V); ceq += (k == V);
    }
    // block exclusive scan (warp shfl + warp totals)
    int vg = cgt, ve = ceq;
#pragma unroll
    for (int o = 1; o < 32; o <<= 1) {
        int ng = __shfl_up_sync(0xffffffffu, vg, o);
        int ne = __shfl_up_sync(0xffffffffu, ve, o);
        if (lane >= o) { vg += ng; ve += ne; }
    }
    if (lane == 31) { red[2 + warp] = vg; red[34 + warp] = ve; }
    __syncthreads();
    if (tid < 32) {
        int wg = red[2 + tid], we = red[34 + tid];
#pragma unroll
        for (int o = 1; o < 32; o <<= 1) {
            int ng = __shfl_up_sync(0xffffffffu, wg, o);
            int ne = __shfl_up_sync(0xffffffffu, we, o);
            if (tid >= o) { wg += ng; we += ne; }
        }
        red[2 + tid] = wg; red[34 + tid] = we;
    }
    __syncthreads();
    int base_gt = vg - cgt + (warp ? red[2 + warp - 1] : 0);
    int base_eq = ve - ceq + (warp ? red[34 + warp - 1] : 0);
    const int count_gt = red[2 + 31];
    const int need_eq  = MAXP - count_gt;

    // scatter: all >V anywhere in [0,count_gt); ties (==V) by lowest idx into tail
    for (int j = beg; j < beg + 32; j++) {
        unsigned k = keys[j];
        if (k > V) {
            sbuf[base_gt++] = ((unsigned long long)(~k) << 32) | (unsigned)j;
        } else if (k == V) {
            int r = base_eq++;
            if (r < need_eq)
                sbuf[count_gt + r] = ((unsigned long long)(~V) << 32) | (unsigned)j;
        }
    }

    // bitonic sort ascending on (~key, idx)  => key desc, idx asc on ties
    for (int size = 2; size <= MAXP; size <<= 1) {
        for (int stride = size >> 1; stride > 0; stride >>= 1) {
            __syncthreads();
#pragma unroll
            for (int q = 0; q < 4; q++) {
                int t = tid + q * 1024;
                int pos = 2 * t - (t & (stride - 1));
                bool asc = ((pos & size) == 0);
                unsigned long long a = sbuf[pos], b = sbuf[pos + stride];
                if ((a > b) == asc) { sbuf[pos] = b; sbuf[pos + stride] = a; }
            }
        }
    }
    __syncthreads();

    // softmax over first `budget` entries
    const float s0 = key2f(~(unsigned)(sbuf[0] >> 32));
    const int budget = g_budget;
    float part = 0.0f;
    float ev[8]; int iv[8];
#pragma unroll
    for (int i = 0; i < 8; i++) {
        int p = tid + i * 1024;
        unsigned long long v = sbuf[p];
        unsigned key = ~(unsigned)(v >> 32);
        iv[i] = (int)(v & 0xFFFFFFFFu);
        float e = (p < budget) ? expf(key2f(key) - s0) : 0.0f;
        ev[i] = e;
        part += e;
    }
#pragma unroll
    for (int o = 16; o > 0; o >>= 1) part += __shfl_down_sync(0xffffffffu, part, o);
    __syncthreads();
    if (lane == 0) fred[64 + warp] = part;
    __syncthreads();
    if (tid == 0) {
        float s = 0.0f;
        for (int w = 0; w < 32; w++) s += fred[64 + w];
        fred[96] = s;
    }
    __syncthreads();
    const float denom = fred[96];

#pragma unroll
    for (int i = 0; i < 8; i++) {
        int p = tid + i * 1024;
        out_idx[(size_t)row * MAXP + p] = (float)iv[i];
        out_w  [(size_t)row * MAXP + p] = ev[i] / denom;
    }
}

// ---------------- launch -----------------------------------------------------
extern "C" void kernel_launch(void* const* d_in, const int* in_sizes, int n_in,
                              void* d_out, int out_size)
{
    const float* x    = (const float*)d_in[0];
    const float* noise= (const float*)d_in[1];
    const float* W1c  = (const float*)d_in[2];
    const float* b1c  = (const float*)d_in[3];
    const float* W2c  = (const float*)d_in[4];
    const float* b2c  = (const float*)d_in[5];
    const float* Ws1  = (const float*)d_in[6];
    const float* bs1  = (const float*)d_in[7];
    const float* Ws2  = (const float*)d_in[8];
    const float* bs2  = (const float*)d_in[9];

    float* out        = (float*)d_out;
    float* out_idx    = out;
    float* out_budget = out + (size_t)BATCH * MAXP;
    float* out_w      = out_budget + 1;
    float* out_comp   = out_w + (size_t)BATCH * MAXP;

    float *c1p, *hp, *sp;
    cudaGetSymbolAddress((void**)&c1p, g_c1);
    cudaGetSymbolAddress((void**)&hp,  g_h);
    cudaGetSymbolAddress((void**)&sp,  g_scores);

    // complexity net
    sgemm128<<<dim3(1, 16), 256>>>(x, W1c, b1c, nullptr, c1p, BATCH, 128, IN_DIM, 0);
    comp_kernel<<<256, 256>>>(W2c, b2c, out_comp);
    budget_kernel<<<1, 1024>>>(out_budget);

    // scorer
    sgemm128<<<dim3(8, 16), 256>>>(x, Ws1, bs1, nullptr, hp, BATCH, HIDN, IN_DIM, 0);
    sgemm128<<<dim3(256, 16), 256>>>(hp, Ws2, bs2, noise, sp, BATCH, POOLN, HIDN, 1);

    // top-k + softmax
    cudaFuncSetAttribute(topk_kernel, cudaFuncAttributeMaxDynamicSharedMemorySize, TOPK_SMEM);
    topk_kernel<<<BATCH, 1024, TOPK_SMEM>>>(out_idx, out_w);
}